// round 1
// baseline (speedup 1.0000x reference)
#include <cuda_runtime.h>

#define N_NODES 50000
#define N_EDGES 1600000
#define FDIM 128
#define CDIM 64

// Scratch (allocation-free rule: __device__ globals)
__device__ float g_deg[N_NODES];
__device__ float g_isd[N_NODES];
__device__ float g_bufA[(size_t)N_NODES * FDIM];
__device__ float g_bufB[(size_t)N_NODES * FDIM];

__global__ void k_deg_init() {
    int i = blockIdx.x * blockDim.x + threadIdx.x;
    if (i < N_NODES) g_deg[i] = 1.0f;  // self-loop contribution
}

__global__ void k_deg_acc(const float* __restrict__ data, const int* __restrict__ idx) {
    int e = blockIdx.x * blockDim.x + threadIdx.x;
    if (e < N_EDGES) atomicAdd(&g_deg[idx[2 * e]], data[e]);
}

__global__ void k_isd() {
    int i = blockIdx.x * blockDim.x + threadIdx.x;
    if (i < N_NODES) g_isd[i] = rsqrtf(g_deg[i]);
}

// xout[i] = isd[i]^2 * xin[i]   (self-loop term of normalized A+I)
__global__ void k_self_init(const float* __restrict__ xin, float* __restrict__ xout) {
    int idx = blockIdx.x * blockDim.x + threadIdx.x;   // over N*F/4 float4s
    if (idx < N_NODES * (FDIM / 4)) {
        int i = idx >> 5;  // FDIM/4 == 32
        float s = g_isd[i];
        s = s * s;
        float4 x = reinterpret_cast<const float4*>(xin)[idx];
        x.x *= s; x.y *= s; x.z *= s; x.w *= s;
        reinterpret_cast<float4*>(xout)[idx] = x;
    }
}

// Warp-per-edge SpMM: xout[row] += (data[e]*isd[row]*isd[col]) * xin[col]
__global__ void k_spmm(const float* __restrict__ xin, float* __restrict__ xout,
                       const float* __restrict__ data, const int* __restrict__ idx) {
    int e = (blockIdx.x * blockDim.x + threadIdx.x) >> 5;
    int lane = threadIdx.x & 31;
    if (e >= N_EDGES) return;
    int2 rc = reinterpret_cast<const int2*>(idx)[e];     // broadcast within warp
    float v = data[e] * g_isd[rc.x] * g_isd[rc.y];
    float4 x = reinterpret_cast<const float4*>(xin + (size_t)rc.y * FDIM)[lane];
    float* dst = xout + (size_t)rc.x * FDIM + lane * 4;  // 16B aligned
    asm volatile("red.global.add.v4.f32 [%0], {%1, %2, %3, %4};"
                 :: "l"(dst), "f"(v * x.x), "f"(v * x.y), "f"(v * x.z), "f"(v * x.w)
                 : "memory");
}

// out[i][c] = dot(z[i], w[c]) + bias[c]. W transposed in smem (bank-conflict-free).
__global__ void k_linear(const float* __restrict__ z, const float* __restrict__ w,
                         const float* __restrict__ bias, float* __restrict__ out) {
    __shared__ float Ws[FDIM * CDIM];  // [k][c] layout, 32 KB
    int c = threadIdx.x;               // 0..63
    int y = threadIdx.y;               // 0..3
    int tid = y * 64 + c;
    for (int t = tid; t < CDIM * FDIM; t += 256) {
        int cc = t / FDIM, kk = t % FDIM;
        Ws[kk * CDIM + cc] = w[t];
    }
    __syncthreads();
    float b = bias[c];
    int base = blockIdx.x * 8;
#pragma unroll
    for (int j = 0; j < 2; j++) {
        int i = base + y * 2 + j;
        if (i < N_NODES) {
            const float4* zr = reinterpret_cast<const float4*>(z + (size_t)i * FDIM);
            float acc = b;
#pragma unroll
            for (int k4 = 0; k4 < FDIM / 4; k4++) {
                float4 zz = zr[k4];
                int k = k4 * 4;
                acc += zz.x * Ws[(k + 0) * CDIM + c];
                acc += zz.y * Ws[(k + 1) * CDIM + c];
                acc += zz.z * Ws[(k + 2) * CDIM + c];
                acc += zz.w * Ws[(k + 3) * CDIM + c];
            }
            out[(size_t)i * CDIM + c] = acc;
        }
    }
}

extern "C" void kernel_launch(void* const* d_in, const int* in_sizes, int n_in,
                              void* d_out, int out_size) {
    const float* X      = (const float*)d_in[0];
    const float* A_data = (const float*)d_in[1];
    const int*   A_idx  = (const int*)d_in[2];
    const float* Wt     = (const float*)d_in[3];
    const float* bias   = (const float*)d_in[4];
    float* out = (float*)d_out;

    float *bufA, *bufB;
    cudaGetSymbolAddress((void**)&bufA, g_bufA);
    cudaGetSymbolAddress((void**)&bufB, g_bufB);

    // 1) degree + inv-sqrt-degree
    k_deg_init<<<(N_NODES + 255) / 256, 256>>>();
    k_deg_acc<<<(N_EDGES + 255) / 256, 256>>>(A_data, A_idx);
    k_isd<<<(N_NODES + 255) / 256, 256>>>();

    const int nvec = N_NODES * (FDIM / 4);

    // 2) layer 1: bufA = A' X
    k_self_init<<<(nvec + 255) / 256, 256>>>(X, bufA);
    k_spmm<<<(N_EDGES * 32 + 255) / 256, 256>>>(X, bufA, A_data, A_idx);

    // 3) layer 2: bufB = A' bufA
    k_self_init<<<(nvec + 255) / 256, 256>>>(bufA, bufB);
    k_spmm<<<(N_EDGES * 32 + 255) / 256, 256>>>(bufA, bufB, A_data, A_idx);

    // 4) out = bufB @ W^T + bias
    k_linear<<<(N_NODES + 7) / 8, dim3(64, 4)>>>(bufB, Wt, bias, out);
}